// round 11
// baseline (speedup 1.0000x reference)
#include <cuda_runtime.h>
#include <cuda_bf16.h>
#include <math.h>
#include <stdint.h>

// ---------------------------------------------------------------------------
// QuantumEncoderLayer: B=32, S=512, d=512, H=4, hd=128, nq=8, DIM=256, L=4
// GEMMs + attention on tensor cores via split-bf16 (hi+lo) warp MMA.
// R10: QKV emits split bf16; attention consumes bf16 with cp.async K
// prefetch; GEMM 3-stage single-sync pipeline; LN1+angles fused.
// ---------------------------------------------------------------------------

#define ROWS_TOTAL 16384   // B*S

// fp32 scratch
__device__ float g_y   [ROWS_TOTAL * 512];
__device__ float g_x1  [ROWS_TOTAL * 512];
__device__ float g_x2  [ROWS_TOTAL * 512];
__device__ float g_ang [ROWS_TOTAL * 8];
__device__ float g_zv  [ROWS_TOTAL * 8];

// split bf16 scratch
__device__ __nv_bfloat16 g_qkvh[ROWS_TOTAL * 1536], g_qkvl[ROWS_TOTAL * 1536];
__device__ __nv_bfloat16 g_xh [ROWS_TOTAL * 512], g_xl [ROWS_TOTAL * 512];
__device__ __nv_bfloat16 g_ah [ROWS_TOTAL * 512], g_al [ROWS_TOTAL * 512];
__device__ __nv_bfloat16 g_x2h[ROWS_TOTAL * 512], g_x2l[ROWS_TOTAL * 512];
__device__ __nv_bfloat16 g_hh [ROWS_TOTAL * 2048], g_hl[ROWS_TOTAL * 2048];
__device__ __nv_bfloat16 g_wah[1536 * 512], g_wal[1536 * 512];
__device__ __nv_bfloat16 g_woh[512 * 512],  g_wol[512 * 512];
__device__ __nv_bfloat16 g_w1h[2048 * 512], g_w1l[2048 * 512];
__device__ __nv_bfloat16 g_w2h[512 * 2048], g_w2l[512 * 2048];

// ---------------------------------------------------------------------------
// helpers
// ---------------------------------------------------------------------------
__device__ __forceinline__ uint32_t smem_u32(const void* p) {
    return (uint32_t)__cvta_generic_to_shared(p);
}
__device__ __forceinline__ void ldsm4(uint32_t* r, uint32_t a) {
    asm volatile("ldmatrix.sync.aligned.m8n8.x4.shared.b16 {%0,%1,%2,%3}, [%4];\n"
                 : "=r"(r[0]), "=r"(r[1]), "=r"(r[2]), "=r"(r[3]) : "r"(a));
}
__device__ __forceinline__ void mma16816(float* d, const uint32_t* a,
                                         const uint32_t* b) {
    asm volatile("mma.sync.aligned.m16n8k16.row.col.f32.bf16.bf16.f32 "
                 "{%0,%1,%2,%3}, {%4,%5,%6,%7}, {%8,%9}, {%0,%1,%2,%3};\n"
                 : "+f"(d[0]), "+f"(d[1]), "+f"(d[2]), "+f"(d[3])
                 : "r"(a[0]), "r"(a[1]), "r"(a[2]), "r"(a[3]),
                   "r"(b[0]), "r"(b[1]));
}
__device__ __forceinline__ void cpa16(uint32_t saddr, const void* gaddr) {
    asm volatile("cp.async.cg.shared.global [%0], [%1], 16;\n"
                 :: "r"(saddr), "l"(gaddr));
}
#define CPA_COMMIT() asm volatile("cp.async.commit_group;\n")
template<int NW>
__device__ __forceinline__ void cp_wait() {
    asm volatile("cp.async.wait_group %0;\n" :: "n"(NW));
}
__device__ __forceinline__ uint32_t split2(float a, float b, uint32_t& lo) {
    __nv_bfloat16 ha = __float2bfloat16(a), hb = __float2bfloat16(b);
    __nv_bfloat16 la = __float2bfloat16(a - __bfloat162float(ha));
    __nv_bfloat16 lb = __float2bfloat16(b - __bfloat162float(hb));
    lo = (uint32_t)__bfloat16_as_ushort(la) |
         ((uint32_t)__bfloat16_as_ushort(lb) << 16);
    return (uint32_t)__bfloat16_as_ushort(ha) |
           ((uint32_t)__bfloat16_as_ushort(hb) << 16);
}

// ---------------------------------------------------------------------------
// k_split: fp32 -> (hi, lo) bf16, elementwise. n % 1024 == 0.
// ---------------------------------------------------------------------------
__global__ void k_split(const float* __restrict__ in,
                        __nv_bfloat16* __restrict__ hi,
                        __nv_bfloat16* __restrict__ lo, int n)
{
    int base = (blockIdx.x * 256 + threadIdx.x) * 4;
    if (base >= n) return;
    float4 v = *(const float4*)(in + base);
    uint32_t l0, l1;
    uint32_t h0 = split2(v.x, v.y, l0);
    uint32_t h1 = split2(v.z, v.w, l1);
    *(uint2*)(hi + base) = make_uint2(h0, h1);
    *(uint2*)(lo + base) = make_uint2(l0, l1);
}

// ===========================================================================
// Tensor-core GEMM: C = A @ B^T + bias. split-bf16, 3-stage cp.async,
// one __syncthreads per k-iter.
// EPI: 0 none, 1 exact GELU, 2 += R.  OUT: 0 fp32 C, 1 split bf16 (Ch,Cl).
// ===========================================================================
#define LDSD 40
#define AE   (128 * LDSD)
#define AB   (AE * 2)
#define STAGEB (AB * 4)        // 40960
#define GSMEM  (STAGEB * 3)    // 122880

template<int EPI, int OUT>
__global__ void __launch_bounds__(256) k_tgemm2(
    const __nv_bfloat16* __restrict__ Ah, const __nv_bfloat16* __restrict__ Al,
    const __nv_bfloat16* __restrict__ Bh, const __nv_bfloat16* __restrict__ Bl,
    const float* __restrict__ bias, const float* __restrict__ R,
    float* __restrict__ C,
    __nv_bfloat16* __restrict__ Ch, __nv_bfloat16* __restrict__ Cl,
    int N, int K)
{
    extern __shared__ __nv_bfloat16 dsm[];
    const uint32_t sbase = smem_u32(dsm);

    const int tid = threadIdx.x;
    const int lane = tid & 31, warp = tid >> 5;
    const int wm = warp & 3, wn = warp >> 2;
    const int m0 = blockIdx.y * 128, n0 = blockIdx.x * 128;

    const int crow = tid >> 2;
    const int ccol = (tid & 3) * 8;
    const __nv_bfloat16* Agh = Ah + (size_t)(m0 + crow) * K + ccol;
    const __nv_bfloat16* Agl = Al + (size_t)(m0 + crow) * K + ccol;
    const __nv_bfloat16* Bgh = Bh + (size_t)(n0 + crow) * K + ccol;
    const __nv_bfloat16* Bgl = Bl + (size_t)(n0 + crow) * K + ccol;
    const uint32_t so_base = (uint32_t)(crow * LDSD + ccol) * 2;
    const uint32_t so_step = (uint32_t)(64 * LDSD) * 2;

    float acc[2][8][4];
#pragma unroll
    for (int i = 0; i < 2; i++)
#pragma unroll
        for (int j = 0; j < 8; j++)
#pragma unroll
            for (int q = 0; q < 4; q++) acc[i][j][q] = 0.f;

    auto issue_stage = [&](int it, int st) {
        const int k0 = it * 32;
        const uint32_t sb = sbase + st * STAGEB;
#pragma unroll
        for (int r2 = 0; r2 < 2; r2++) {
            const size_t go = (size_t)r2 * 64 * K + k0;
            const uint32_t so = so_base + r2 * so_step;
            cpa16(sb + 0 * AB + so, Agh + go);
            cpa16(sb + 1 * AB + so, Agl + go);
            cpa16(sb + 2 * AB + so, Bgh + go);
            cpa16(sb + 3 * AB + so, Bgl + go);
        }
    };

    const int niter = K >> 5;
    issue_stage(0, 0);
    CPA_COMMIT();
    issue_stage(1, 1);
    CPA_COMMIT();

    for (int it = 0; it < niter; it++) {
        if (it + 1 < niter) cp_wait<1>(); else cp_wait<0>();
        __syncthreads();
        if (it + 2 < niter) { issue_stage(it + 2, (it + 2) % 3); CPA_COMMIT(); }

        const uint32_t sb = sbase + (it % 3) * STAGEB;
        const uint32_t aH = sb, aL = sb + AB, bH = sb + 2 * AB, bL = sb + 3 * AB;

#pragma unroll
        for (int ks = 0; ks < 2; ks++) {
            const int kk = ks * 16;
            uint32_t ah[2][4], al2[2][4], bh[8][2], bl[8][2];
#pragma unroll
            for (int ms = 0; ms < 2; ms++) {
                int row = wm * 32 + ms * 16 + ((lane >> 3) & 1) * 8 + (lane & 7);
                int col = kk + ((lane >> 4) & 1) * 8;
                uint32_t bo = (uint32_t)(row * LDSD + col) * 2;
                ldsm4(ah[ms], aH + bo);
                ldsm4(al2[ms], aL + bo);
            }
#pragma unroll
            for (int nb = 0; nb < 4; nb++) {
                int rn = wn * 64 + nb * 16 + ((lane >> 4) & 1) * 8 + (lane & 7);
                int col = kk + ((lane >> 3) & 1) * 8;
                uint32_t bo = (uint32_t)(rn * LDSD + col) * 2;
                uint32_t t4[4];
                ldsm4(t4, bH + bo);
                bh[2 * nb][0] = t4[0]; bh[2 * nb][1] = t4[1];
                bh[2 * nb + 1][0] = t4[2]; bh[2 * nb + 1][1] = t4[3];
                ldsm4(t4, bL + bo);
                bl[2 * nb][0] = t4[0]; bl[2 * nb][1] = t4[1];
                bl[2 * nb + 1][0] = t4[2]; bl[2 * nb + 1][1] = t4[3];
            }
#pragma unroll
            for (int ms = 0; ms < 2; ms++)
#pragma unroll
                for (int ns = 0; ns < 8; ns++) {
                    mma16816(acc[ms][ns], ah[ms], bh[ns]);
                    mma16816(acc[ms][ns], ah[ms], bl[ns]);
                    mma16816(acc[ms][ns], al2[ms], bh[ns]);
                }
        }
    }

    const int tg = lane >> 2, tq = lane & 3;
#pragma unroll
    for (int ms = 0; ms < 2; ms++) {
        int row0 = m0 + wm * 32 + ms * 16 + tg;
#pragma unroll
        for (int ns = 0; ns < 8; ns++) {
            int col = n0 + wn * 64 + ns * 8 + tq * 2;
            float b0 = bias[col], b1 = bias[col + 1];
            float v[4];
            v[0] = acc[ms][ns][0] + b0; v[1] = acc[ms][ns][1] + b1;
            v[2] = acc[ms][ns][2] + b0; v[3] = acc[ms][ns][3] + b1;
            if (EPI == 1) {
#pragma unroll
                for (int q = 0; q < 4; q++)
                    v[q] = 0.5f * v[q] *
                           (1.0f + erff(v[q] * 0.7071067811865476f));
            }
            size_t o0 = (size_t)row0 * N + col;
            size_t o1 = (size_t)(row0 + 8) * N + col;
            if (EPI == 2) {
                float2 r0 = *(const float2*)(R + o0);
                float2 r1 = *(const float2*)(R + o1);
                v[0] += r0.x; v[1] += r0.y; v[2] += r1.x; v[3] += r1.y;
            }
            if (OUT == 0) {
                *(float2*)(C + o0) = make_float2(v[0], v[1]);
                *(float2*)(C + o1) = make_float2(v[2], v[3]);
            } else {
                uint32_t l0, l1;
                uint32_t h0 = split2(v[0], v[1], l0);
                uint32_t h1 = split2(v[2], v[3], l1);
                *(uint32_t*)(Ch + o0) = h0; *(uint32_t*)(Cl + o0) = l0;
                *(uint32_t*)(Ch + o1) = h1; *(uint32_t*)(Cl + o1) = l1;
            }
        }
    }
}

// ===========================================================================
// Tensor-core flash attention v2: consumes split-bf16 qkv.
// Q + K via cp.async (K double-buffered); V fill = bf16 register scatter.
// Frag/mma layout identical to verified R9 kernel.
// ===========================================================================
#define QSTRIDE 136
#define VSTRIDE 72
#define FA_QE (128 * QSTRIDE)       // 17408
#define FA_KE (64 * QSTRIDE)        // 8704
#define FA_VE (128 * VSTRIDE)       // 9216
// layout: Qh, Ql, Kh(st0), Kh(st1), Kl(st0), Kl(st1), Vh, Vl
#define FA_ELEMS (2*FA_QE + 4*FA_KE + 2*FA_VE)   // 88064
#define FA_SMEM (FA_ELEMS * 2)                   // 176128 B

__global__ void __launch_bounds__(256, 1) k_attn_tc(
    const __nv_bfloat16* __restrict__ qkvh,
    const __nv_bfloat16* __restrict__ qkvl,
    __nv_bfloat16* __restrict__ oh, __nv_bfloat16* __restrict__ ol)
{
    extern __shared__ __nv_bfloat16 smb[];
    __nv_bfloat16* sQh = smb;
    __nv_bfloat16* sQl = smb + FA_QE;
    __nv_bfloat16* sKh = smb + 2 * FA_QE;                 // two stages
    __nv_bfloat16* sKl = smb + 2 * FA_QE + 2 * FA_KE;     // two stages
    __nv_bfloat16* sVh = smb + 2 * FA_QE + 4 * FA_KE;
    __nv_bfloat16* sVl = smb + 2 * FA_QE + 4 * FA_KE + FA_VE;

    const int tid = threadIdx.x, lane = tid & 31, warp = tid >> 5;
    const int qt = blockIdx.x, bh = blockIdx.y;
    const int b = bh >> 2, h = bh & 3;
    const size_t bhbase = (size_t)b * 512 * 1536 + h * 128;
    const float scale = 0.08838834764831845f;   // 1/sqrt(128)

    const uint32_t uQh = smem_u32(sQh), uQl = smem_u32(sQl);
    const uint32_t uKh = smem_u32(sKh), uKl = smem_u32(sKl);
    const uint32_t uVh = smem_u32(sVh), uVl = smem_u32(sVl);

    // ---- Q tile via cp.async ----
    {
        int r = tid >> 1, c0 = (tid & 1) * 64;
        const __nv_bfloat16* gqh = qkvh + bhbase + (size_t)(qt * 128 + r) * 1536 + c0;
        const __nv_bfloat16* gql = qkvl + bhbase + (size_t)(qt * 128 + r) * 1536 + c0;
        uint32_t so = (uint32_t)(r * QSTRIDE + c0) * 2;
#pragma unroll
        for (int i = 0; i < 8; i++) cpa16(uQh + so + i * 16, gqh + i * 8);
#pragma unroll
        for (int i = 0; i < 8; i++) cpa16(uQl + so + i * 16, gql + i * 8);
    }
    CPA_COMMIT();

    auto issueK = [&](int kc, int st) {
        int r = tid >> 2, c0 = (tid & 3) * 32;
        const __nv_bfloat16* gkh =
            qkvh + bhbase + (size_t)(kc * 64 + r) * 1536 + 512 + c0;
        const __nv_bfloat16* gkl =
            qkvl + bhbase + (size_t)(kc * 64 + r) * 1536 + 512 + c0;
        uint32_t so = (uint32_t)(r * QSTRIDE + c0) * 2;
        uint32_t sto = (uint32_t)(st * FA_KE) * 2;
#pragma unroll
        for (int i = 0; i < 4; i++) cpa16(uKh + sto + so + i * 16, gkh + i * 8);
#pragma unroll
        for (int i = 0; i < 4; i++) cpa16(uKl + sto + so + i * 16, gkl + i * 8);
    };

    issueK(0, 0);
    CPA_COMMIT();

    float o[16][4];
#pragma unroll
    for (int j = 0; j < 16; j++)
#pragma unroll
        for (int q = 0; q < 4; q++) o[j][q] = 0.f;
    float mr0 = -INFINITY, mr1 = -INFINITY, lr0 = 0.f, lr1 = 0.f;

    for (int kc = 0; kc < 8; kc++) {
        const int st = kc & 1;
        __syncthreads();      // V buffer free (PV kc-1 done); K stage st^1 free

        // ---- V fill: bf16 pairs, conflict-free scatter (d = 2q + 8i) ----
        {
            int r = tid >> 2, q = tid & 3;
            const size_t vg = bhbase + (size_t)(kc * 64 + r) * 1536 + 1024;
#pragma unroll
            for (int i = 0; i < 16; i++) {
                int d = q * 2 + i * 8;
                __nv_bfloat162 vh = *(const __nv_bfloat162*)(qkvh + vg + d);
                __nv_bfloat162 vl = *(const __nv_bfloat162*)(qkvl + vg + d);
                sVh[d * VSTRIDE + r] = vh.x; sVh[(d + 1) * VSTRIDE + r] = vh.y;
                sVl[d * VSTRIDE + r] = vl.x; sVl[(d + 1) * VSTRIDE + r] = vl.y;
            }
        }
        if (kc + 1 < 8) { issueK(kc + 1, st ^ 1); CPA_COMMIT(); }
        if (kc + 1 < 8) cp_wait<1>(); else cp_wait<0>();
        __syncthreads();

        const uint32_t kH = uKh + (uint32_t)(st * FA_KE) * 2;
        const uint32_t kL = uKl + (uint32_t)(st * FA_KE) * 2;

        // ---- scores: S(16 x 64) per warp ----
        float sc[8][4];
#pragma unroll
        for (int j = 0; j < 8; j++)
#pragma unroll
            for (int q = 0; q < 4; q++) sc[j][q] = 0.f;

#pragma unroll
        for (int ks = 0; ks < 8; ks++) {
            const int kk = ks * 16;
            uint32_t ah[4], al2[4];
            int arow = warp * 16 + ((lane >> 3) & 1) * 8 + (lane & 7);
            int acol = kk + ((lane >> 4) & 1) * 8;
            uint32_t ao = (uint32_t)(arow * QSTRIDE + acol) * 2;
            ldsm4(ah, uQh + ao);
            ldsm4(al2, uQl + ao);
#pragma unroll
            for (int nb = 0; nb < 4; nb++) {
                int rn = nb * 16 + ((lane >> 4) & 1) * 8 + (lane & 7);
                int col = kk + ((lane >> 3) & 1) * 8;
                uint32_t bo = (uint32_t)(rn * QSTRIDE + col) * 2;
                uint32_t th[4], tl[4];
                ldsm4(th, kH + bo);
                ldsm4(tl, kL + bo);
                uint32_t b0h[2] = {th[0], th[1]}, b1h[2] = {th[2], th[3]};
                uint32_t b0l[2] = {tl[0], tl[1]}, b1l[2] = {tl[2], tl[3]};
                mma16816(sc[2*nb],   ah, b0h);
                mma16816(sc[2*nb],   ah, b0l);
                mma16816(sc[2*nb],   al2, b0h);
                mma16816(sc[2*nb+1], ah, b1h);
                mma16816(sc[2*nb+1], ah, b1l);
                mma16816(sc[2*nb+1], al2, b1h);
            }
        }

        // ---- online softmax ----
        float mx0 = -INFINITY, mx1 = -INFINITY;
#pragma unroll
        for (int j = 0; j < 8; j++) {
#pragma unroll
            for (int q = 0; q < 4; q++) sc[j][q] *= scale;
            mx0 = fmaxf(mx0, fmaxf(sc[j][0], sc[j][1]));
            mx1 = fmaxf(mx1, fmaxf(sc[j][2], sc[j][3]));
        }
        mx0 = fmaxf(mx0, __shfl_xor_sync(0xffffffffu, mx0, 1));
        mx0 = fmaxf(mx0, __shfl_xor_sync(0xffffffffu, mx0, 2));
        mx1 = fmaxf(mx1, __shfl_xor_sync(0xffffffffu, mx1, 1));
        mx1 = fmaxf(mx1, __shfl_xor_sync(0xffffffffu, mx1, 2));
        float mn0 = fmaxf(mr0, mx0), mn1 = fmaxf(mr1, mx1);
        float a0 = __expf(mr0 - mn0), a1 = __expf(mr1 - mn1);

        uint32_t phk[8][2], plk[8][2];
        float s0 = 0.f, s1 = 0.f;
#pragma unroll
        for (int j = 0; j < 8; j++) {
            float p0 = __expf(sc[j][0] - mn0);
            float p1 = __expf(sc[j][1] - mn0);
            float p2 = __expf(sc[j][2] - mn1);
            float p3 = __expf(sc[j][3] - mn1);
            s0 += p0 + p1; s1 += p2 + p3;
            phk[j][0] = split2(p0, p1, plk[j][0]);
            phk[j][1] = split2(p2, p3, plk[j][1]);
        }
        s0 += __shfl_xor_sync(0xffffffffu, s0, 1);
        s0 += __shfl_xor_sync(0xffffffffu, s0, 2);
        s1 += __shfl_xor_sync(0xffffffffu, s1, 1);
        s1 += __shfl_xor_sync(0xffffffffu, s1, 2);
        lr0 = lr0 * a0 + s0;
        lr1 = lr1 * a1 + s1;
#pragma unroll
        for (int j = 0; j < 16; j++) {
            o[j][0] *= a0; o[j][1] *= a0;
            o[j][2] *= a1; o[j][3] *= a1;
        }
        mr0 = mn0; mr1 = mn1;

        // ---- P @ V ----
#pragma unroll
        for (int jp = 0; jp < 4; jp++) {
            uint32_t pah[4] = {phk[2*jp][0], phk[2*jp][1],
                               phk[2*jp+1][0], phk[2*jp+1][1]};
            uint32_t pal[4] = {plk[2*jp][0], plk[2*jp][1],
                               plk[2*jp+1][0], plk[2*jp+1][1]};
            int col = jp * 16 + ((lane >> 3) & 1) * 8;
#pragma unroll
            for (int nb = 0; nb < 8; nb++) {
                int rn = nb * 16 + ((lane >> 4) & 1) * 8 + (lane & 7);
                uint32_t bo = (uint32_t)(rn * VSTRIDE + col) * 2;
                uint32_t th[4], tl[4];
                ldsm4(th, uVh + bo);
                ldsm4(tl, uVl + bo);
                uint32_t b0h[2] = {th[0], th[1]}, b1h[2] = {th[2], th[3]};
                uint32_t b0l[2] = {tl[0], tl[1]}, b1l[2] = {tl[2], tl[3]};
                mma16816(o[2*nb],   pah, b0h);
                mma16816(o[2*nb],   pah, b0l);
                mma16816(o[2*nb],   pal, b0h);
                mma16816(o[2*nb+1], pah, b1h);
                mma16816(o[2*nb+1], pah, b1l);
                mma16816(o[2*nb+1], pal, b1h);
            }
        }
    }

    // ---- epilogue ----
    const int g = lane >> 2, q = lane & 3;
    const int row0 = qt * 128 + warp * 16 + g;
    const float i0 = 1.f / lr0, i1 = 1.f / lr1;
#pragma unroll
    for (int j = 0; j < 16; j++) {
        int col = h * 128 + j * 8 + q * 2;
        size_t off0 = ((size_t)b * 512 + row0) * 512 + col;
        size_t off1 = off0 + (size_t)8 * 512;
        uint32_t lo;
        uint32_t hi = split2(o[j][0] * i0, o[j][1] * i0, lo);
        *(uint32_t*)(oh + off0) = hi; *(uint32_t*)(ol + off0) = lo;
        hi = split2(o[j][2] * i1, o[j][3] * i1, lo);
        *(uint32_t*)(oh + off1) = hi; *(uint32_t*)(ol + off1) = lo;
    }
}

// ===========================================================================
// LayerNorm (LN2 final): one warp per row.
// ===========================================================================
__global__ void k_ln(const float* __restrict__ in, const float* __restrict__ g,
                     const float* __restrict__ b, float* __restrict__ out)
{
    const int warp = threadIdx.x >> 5, lane = threadIdx.x & 31;
    const int row = blockIdx.x * 8 + warp;
    const float* p = in + (size_t)row * 512;
    float v[16]; float s = 0.f;
#pragma unroll
    for (int j = 0; j < 16; j++) { v[j] = p[j * 32 + lane]; s += v[j]; }
#pragma unroll
    for (int m = 16; m > 0; m >>= 1) s += __shfl_xor_sync(0xffffffffu, s, m);
    float mean = s * (1.f / 512.f);
    float vs = 0.f;
#pragma unroll
    for (int j = 0; j < 16; j++) { float d = v[j] - mean; vs += d * d; }
#pragma unroll
    for (int m = 16; m > 0; m >>= 1) vs += __shfl_xor_sync(0xffffffffu, vs, m);
    float inv = rsqrtf(vs * (1.f / 512.f) + 1e-5f);
    float* o = out + (size_t)row * 512;
#pragma unroll
    for (int j = 0; j < 16; j++) {
        int c = j * 32 + lane;
        o[c] = (v[j] - mean) * inv * g[c] + b[c];
    }
}

// ===========================================================================
// Fused: x1 = LN1(y); ang = LN3(x1) @ qin_w^T + qin_b.
// ===========================================================================
__global__ void k_ln1_ang(const float* __restrict__ y,
                          const float* __restrict__ g1, const float* __restrict__ b1,
                          const float* __restrict__ g3, const float* __restrict__ b3,
                          const float* __restrict__ qw, const float* __restrict__ qb,
                          float* __restrict__ x1, float* __restrict__ ang)
{
    const int warp = threadIdx.x >> 5, lane = threadIdx.x & 31;
    const int row = blockIdx.x * 8 + warp;
    const float* p = y + (size_t)row * 512;
    float v[16]; float s = 0.f;
#pragma unroll
    for (int j = 0; j < 16; j++) { v[j] = p[j * 32 + lane]; s += v[j]; }
#pragma unroll
    for (int m = 16; m > 0; m >>= 1) s += __shfl_xor_sync(0xffffffffu, s, m);
    float mean = s * (1.f / 512.f);
    float vs = 0.f;
#pragma unroll
    for (int j = 0; j < 16; j++) { float d = v[j] - mean; vs += d * d; }
#pragma unroll
    for (int m = 16; m > 0; m >>= 1) vs += __shfl_xor_sync(0xffffffffu, vs, m);
    float inv = rsqrtf(vs * (1.f / 512.f) + 1e-5f);
    float n1[16];
    float* o = x1 + (size_t)row * 512;
    float s2 = 0.f;
#pragma unroll
    for (int j = 0; j < 16; j++) {
        int c = j * 32 + lane;
        n1[j] = (v[j] - mean) * inv * g1[c] + b1[c];
        o[c] = n1[j];
        s2 += n1[j];
    }
    // second LN on x1 row
#pragma unroll
    for (int m = 16; m > 0; m >>= 1) s2 += __shfl_xor_sync(0xffffffffu, s2, m);
    float mean2 = s2 * (1.f / 512.f);
    float vs2 = 0.f;
#pragma unroll
    for (int j = 0; j < 16; j++) { float d = n1[j] - mean2; vs2 += d * d; }
#pragma unroll
    for (int m = 16; m > 0; m >>= 1) vs2 += __shfl_xor_sync(0xffffffffu, vs2, m);
    float inv2 = rsqrtf(vs2 * (1.f / 512.f) + 1e-5f);
    float nn[16];
#pragma unroll
    for (int j = 0; j < 16; j++) {
        int c = j * 32 + lane;
        nn[j] = (n1[j] - mean2) * inv2 * g3[c] + b3[c];
    }
#pragma unroll
    for (int q = 0; q < 8; q++) {
        const float* w = qw + q * 512;
        float d = 0.f;
#pragma unroll
        for (int j = 0; j < 16; j++) d = fmaf(nn[j], w[j * 32 + lane], d);
#pragma unroll
        for (int m = 16; m > 0; m >>= 1) d += __shfl_xor_sync(0xffffffffu, d, m);
        if (lane == 0) ang[(size_t)row * 8 + q] = d + qb[q];
    }
}

// ===========================================================================
// Quantum circuit: one warp per sample. 256 complex amps: 8 per lane.
// ===========================================================================
template<int B>
__device__ __forceinline__ void rx_b(float (&xr)[8], float (&xi)[8],
                                     float c, float sn)
{
    if (B >= 3) {
        const int lm = 1 << (B - 3);
#pragma unroll
        for (int r = 0; r < 8; r++) {
            float pr = __shfl_xor_sync(0xffffffffu, xr[r], lm);
            float pi = __shfl_xor_sync(0xffffffffu, xi[r], lm);
            float nr = c * xr[r] + sn * pi;
            float ni = c * xi[r] - sn * pr;
            xr[r] = nr; xi[r] = ni;
        }
    } else {
        const int m = 1 << B;
#pragma unroll
        for (int r = 0; r < 8; r++) {
            if (!(r & m)) {
                int r1 = r | m;
                float ar = xr[r], ai = xi[r], br = xr[r1], bi = xi[r1];
                xr[r]  = c * ar + sn * bi;  xi[r]  = c * ai - sn * br;
                xr[r1] = c * br + sn * ai;  xi[r1] = c * bi - sn * ar;
            }
        }
    }
}

template<int B>
__device__ __forceinline__ void rz_b(float (&xr)[8], float (&xi)[8],
                                     float ch, float sh, int lane)
{
#pragma unroll
    for (int r = 0; r < 8; r++) {
        int bit = (B >= 3) ? ((lane >> (B - 3)) & 1) : ((r >> B) & 1);
        float sgn = bit ? sh : -sh;
        float x = xr[r], y = xi[r];
        xr[r] = x * ch - sgn * y;
        xi[r] = fmaf(x, sgn, y * ch);
    }
}

template<int C>
__device__ __forceinline__ void cnot_c(float (&xr)[8], float (&xi)[8], int lane)
{
    const int cb = 7 - C, tb = 6 - C;
    if (C <= 3) {
        const int lc = 1 << (cb - 3);
        const int tm = 1 << (tb - 3);
        bool ctl = (lane & lc) != 0;
#pragma unroll
        for (int r = 0; r < 8; r++) {
            float pr = __shfl_xor_sync(0xffffffffu, xr[r], tm);
            float pi = __shfl_xor_sync(0xffffffffu, xi[r], tm);
            if (ctl) { xr[r] = pr; xi[r] = pi; }
        }
    } else if (C == 4) {
        if (lane & 1) {
#pragma unroll
            for (int r = 0; r < 4; r++) {
                float t = xr[r]; xr[r] = xr[r + 4]; xr[r + 4] = t;
                t = xi[r]; xi[r] = xi[r + 4]; xi[r + 4] = t;
            }
        }
    } else {
        const int cm = 1 << cb, tm = 1 << tb;
#pragma unroll
        for (int r = 0; r < 8; r++) {
            if ((r & cm) && !(r & tm)) {
                int r1 = r | tm;
                float t = xr[r]; xr[r] = xr[r1]; xr[r1] = t;
                t = xi[r]; xi[r] = xi[r1]; xi[r1] = t;
            }
        }
    }
}

#define DO_RXRZ(BIT, THX, THZ) do {                         \
    float h_, c_, s_;                                       \
    h_ = 0.5f * (THX); sincosf(h_, &s_, &c_);               \
    rx_b<BIT>(xr, xi, c_, s_);                              \
    h_ = 0.5f * (THZ); sincosf(h_, &s_, &c_);               \
    rz_b<BIT>(xr, xi, c_, s_, lane);                        \
} while (0)

__global__ void k_quantum(const float* __restrict__ ang,
                          const float* __restrict__ qw,
                          float* __restrict__ zv)
{
    const int warp = threadIdx.x >> 5, lane = threadIdx.x & 31;
    const int row = blockIdx.x * 8 + warp;
    float a[8];
#pragma unroll
    for (int i = 0; i < 8; i++) a[i] = ang[(size_t)row * 8 + i];

    float xr[8], xi[8];
#pragma unroll
    for (int r = 0; r < 8; r++) { xr[r] = 0.f; xi[r] = 0.f; }
    if (lane == 0) xr[0] = 1.f;

    DO_RXRZ(7, a[0], a[0]);
    DO_RXRZ(6, a[1], a[1]);
    DO_RXRZ(5, a[2], a[2]);
    DO_RXRZ(4, a[3], a[3]);
    DO_RXRZ(3, a[4], a[4]);
    DO_RXRZ(2, a[5], a[5]);
    DO_RXRZ(1, a[6], a[6]);
    DO_RXRZ(0, a[7], a[7]);

    for (int l = 0; l < 4; l++) {
        const float* wl = qw + l * 16;
        DO_RXRZ(7, wl[0], wl[8]);
        DO_RXRZ(6, wl[1], wl[9]);
        DO_RXRZ(5, wl[2], wl[10]);
        DO_RXRZ(4, wl[3], wl[11]);
        DO_RXRZ(3, wl[4], wl[12]);
        DO_RXRZ(2, wl[5], wl[13]);
        DO_RXRZ(1, wl[6], wl[14]);
        DO_RXRZ(0, wl[7], wl[15]);
        cnot_c<0>(xr, xi, lane);
        cnot_c<1>(xr, xi, lane);
        cnot_c<2>(xr, xi, lane);
        cnot_c<3>(xr, xi, lane);
        cnot_c<4>(xr, xi, lane);
        cnot_c<5>(xr, xi, lane);
        cnot_c<6>(xr, xi, lane);
    }

    float p[8], tot = 0.f;
#pragma unroll
    for (int r = 0; r < 8; r++) {
        p[r] = xr[r] * xr[r] + xi[r] * xi[r];
        tot += p[r];
    }
    float z[8];
#pragma unroll
    for (int w = 0; w < 5; w++) {
        int lb = 4 - w;
        z[w] = ((lane >> lb) & 1) ? -tot : tot;
    }
#pragma unroll
    for (int w = 5; w < 8; w++) {
        int bb = 7 - w;
        float s = 0.f;
#pragma unroll
        for (int r = 0; r < 8; r++) s += ((r >> bb) & 1) ? -p[r] : p[r];
        z[w] = s;
    }
#pragma unroll
    for (int i = 0; i < 8; i++)
#pragma unroll
        for (int m = 16; m > 0; m >>= 1)
            z[i] += __shfl_xor_sync(0xffffffffu, z[i], m);
    if (lane == 0) {
#pragma unroll
        for (int i = 0; i < 8; i++) zv[(size_t)row * 8 + i] = z[i];
    }
}

// ===========================================================================
// x2 = x1 + z @ qout_w^T + qout_b; also writes split (x2h, x2l).
// ===========================================================================
__global__ void k_qout(const float* __restrict__ x1, const float* __restrict__ zv,
                       const float* __restrict__ qw, const float* __restrict__ qb,
                       float* __restrict__ x2,
                       __nv_bfloat16* __restrict__ x2h,
                       __nv_bfloat16* __restrict__ x2l)
{
    int idx = blockIdx.x * 256 + threadIdx.x;
    int row = idx >> 7;
    int c = (idx & 127) * 4;
    const float* z = zv + (size_t)row * 8;
    float zz[8];
#pragma unroll
    for (int q = 0; q < 8; q++) zz[q] = z[q];
    float4 r = *(const float4*)(x1 + (size_t)row * 512 + c);
    float rv[4] = {r.x, r.y, r.z, r.w};
    float o[4];
#pragma unroll
    for (int t = 0; t < 4; t++) {
        int col = c + t;
        float acc = qb[col];
        const float* w = qw + col * 8;
#pragma unroll
        for (int q = 0; q < 8; q++) acc = fmaf(zz[q], w[q], acc);
        o[t] = rv[t] + acc;
    }
    size_t off = (size_t)row * 512 + c;
    *(float4*)(x2 + off) = make_float4(o[0], o[1], o[2], o[3]);
    uint32_t l0, l1;
    uint32_t h0 = split2(o[0], o[1], l0);
    uint32_t h1 = split2(o[2], o[3], l1);
    *(uint2*)(x2h + off) = make_uint2(h0, h1);
    *(uint2*)(x2l + off) = make_uint2(l0, l1);
}

// ===========================================================================
extern "C" void kernel_launch(void* const* d_in, const int* in_sizes, int n_in,
                              void* d_out, int out_size)
{
    const float* x          = (const float*)d_in[0];
    const float* attn_in_w  = (const float*)d_in[1];
    const float* attn_in_b  = (const float*)d_in[2];
    const float* attn_out_w = (const float*)d_in[3];
    const float* attn_out_b = (const float*)d_in[4];
    const float* ln1_g      = (const float*)d_in[5];
    const float* ln1_b      = (const float*)d_in[6];
    const float* ln2_g      = (const float*)d_in[7];
    const float* ln2_b      = (const float*)d_in[8];
    const float* ln3_g      = (const float*)d_in[9];
    const float* ln3_b      = (const float*)d_in[10];
    const float* qin_w      = (const float*)d_in[11];
    const float* qin_b      = (const float*)d_in[12];
    const float* qweights   = (const float*)d_in[13];
    const float* qout_w     = (const float*)d_in[14];
    const float* qout_b     = (const float*)d_in[15];
    const float* ffn_w1     = (const float*)d_in[16];
    const float* ffn_b1     = (const float*)d_in[17];
    const float* ffn_w2     = (const float*)d_in[18];
    const float* ffn_b2     = (const float*)d_in[19];
    float* out = (float*)d_out;

    float *y, *x1, *x2, *ang, *zv;
    __nv_bfloat16 *qkvh, *qkvl, *xh, *xl, *ah, *al, *x2h, *x2l, *hh, *hl;
    __nv_bfloat16 *wah, *wal, *woh, *wol, *w1h, *w1l, *w2h, *w2l;
    cudaGetSymbolAddress((void**)&y,    g_y);
    cudaGetSymbolAddress((void**)&x1,   g_x1);
    cudaGetSymbolAddress((void**)&x2,   g_x2);
    cudaGetSymbolAddress((void**)&ang,  g_ang);
    cudaGetSymbolAddress((void**)&zv,   g_zv);
    cudaGetSymbolAddress((void**)&qkvh, g_qkvh);
    cudaGetSymbolAddress((void**)&qkvl, g_qkvl);
    cudaGetSymbolAddress((void**)&xh,   g_xh);
    cudaGetSymbolAddress((void**)&xl,   g_xl);
    cudaGetSymbolAddress((void**)&ah,   g_ah);
    cudaGetSymbolAddress((void**)&al,   g_al);
    cudaGetSymbolAddress((void**)&x2h,  g_x2h);
    cudaGetSymbolAddress((void**)&x2l,  g_x2l);
    cudaGetSymbolAddress((void**)&hh,   g_hh);
    cudaGetSymbolAddress((void**)&hl,   g_hl);
    cudaGetSymbolAddress((void**)&wah,  g_wah);
    cudaGetSymbolAddress((void**)&wal,  g_wal);
    cudaGetSymbolAddress((void**)&woh,  g_woh);
    cudaGetSymbolAddress((void**)&wol,  g_wol);
    cudaGetSymbolAddress((void**)&w1h,  g_w1h);
    cudaGetSymbolAddress((void**)&w1l,  g_w1l);
    cudaGetSymbolAddress((void**)&w2h,  g_w2h);
    cudaGetSymbolAddress((void**)&w2l,  g_w2l);

    cudaFuncSetAttribute(k_attn_tc,
                         cudaFuncAttributeMaxDynamicSharedMemorySize, FA_SMEM);
    cudaFuncSetAttribute(k_tgemm2<0,1>,
                         cudaFuncAttributeMaxDynamicSharedMemorySize, GSMEM);
    cudaFuncSetAttribute(k_tgemm2<2,0>,
                         cudaFuncAttributeMaxDynamicSharedMemorySize, GSMEM);
    cudaFuncSetAttribute(k_tgemm2<1,1>,
                         cudaFuncAttributeMaxDynamicSharedMemorySize, GSMEM);

    // 0. split input + weights to (hi, lo) bf16
    k_split<<<ROWS_TOTAL * 512 / 1024, 256>>>(x, xh, xl, ROWS_TOTAL * 512);
    k_split<<<1536 * 512 / 1024, 256>>>(attn_in_w, wah, wal, 1536 * 512);
    k_split<<<512 * 512 / 1024, 256>>>(attn_out_w, woh, wol, 512 * 512);
    k_split<<<2048 * 512 / 1024, 256>>>(ffn_w1, w1h, w1l, 2048 * 512);
    k_split<<<512 * 2048 / 1024, 256>>>(ffn_w2, w2h, w2l, 512 * 2048);

    // 1. QKV projection -> split bf16 qkv
    k_tgemm2<0,1><<<dim3(12, 128), 256, GSMEM>>>(xh, xl, wah, wal, attn_in_b,
                                                 nullptr, nullptr, qkvh, qkvl,
                                                 1536, 512);
    // 2. Attention (tensor core, bf16 in, split bf16 out)
    k_attn_tc<<<dim3(4, 128), 256, FA_SMEM>>>(qkvh, qkvl, ah, al);
    // 3. Output projection + residual x -> y
    k_tgemm2<2,0><<<dim3(4, 128), 256, GSMEM>>>(ah, al, woh, wol, attn_out_b,
                                                x, y, nullptr, nullptr,
                                                512, 512);
    // 4+5. x1 = LN1(y); angles = LN3(x1) @ qin_w^T + qin_b
    k_ln1_ang<<<2048, 256>>>(y, ln1_g, ln1_b, ln3_g, ln3_b, qin_w, qin_b,
                             x1, ang);
    // 6. quantum expvals
    k_quantum<<<2048, 256>>>(ang, qweights, zv);
    // 7. x2 = x1 + z @ qout_w^T + qout_b (fp32 + split)
    k_qout<<<8192, 256>>>(x1, zv, qout_w, qout_b, x2, x2h, x2l);
    // 8. h = gelu(x2 @ ffn_w1^T + b1), split output
    k_tgemm2<1,1><<<dim3(16, 128), 256, GSMEM>>>(x2h, x2l, w1h, w1l, ffn_b1,
                                                 nullptr, nullptr, hh, hl,
                                                 2048, 512);
    // 9. y = h @ ffn_w2^T + b2 + x2
    k_tgemm2<2,0><<<dim3(4, 128), 256, GSMEM>>>(hh, hl, w2h, w2l, ffn_b2,
                                                x2, y, nullptr, nullptr,
                                                512, 2048);
    // 10. out = LN2(y)
    k_ln<<<2048, 256>>>(y, ln2_g, ln2_b, out);
}

// round 12
// speedup vs baseline: 1.1297x; 1.1297x over previous
#include <cuda_runtime.h>
#include <cuda_bf16.h>
#include <math.h>
#include <stdint.h>

// ---------------------------------------------------------------------------
// QuantumEncoderLayer: B=32, S=512, d=512, H=4, hd=128, nq=8, DIM=256, L=4
// R11: R10 minus the occupancy regression — GEMM back to 2-stage/2-sync
// (81920 B smem -> 2 CTAs/SM). Keeps: QKV split-bf16 output, attention v2
// (bf16 in, cp.async K prefetch), LN1+angles fusion.
// ---------------------------------------------------------------------------

#define ROWS_TOTAL 16384   // B*S

// fp32 scratch
__device__ float g_y   [ROWS_TOTAL * 512];
__device__ float g_x1  [ROWS_TOTAL * 512];
__device__ float g_x2  [ROWS_TOTAL * 512];
__device__ float g_ang [ROWS_TOTAL * 8];
__device__ float g_zv  [ROWS_TOTAL * 8];

// split bf16 scratch
__device__ __nv_bfloat16 g_qkvh[ROWS_TOTAL * 1536], g_qkvl[ROWS_TOTAL * 1536];
__device__ __nv_bfloat16 g_xh [ROWS_TOTAL * 512], g_xl [ROWS_TOTAL * 512];
__device__ __nv_bfloat16 g_ah [ROWS_TOTAL * 512], g_al [ROWS_TOTAL * 512];
__device__ __nv_bfloat16 g_x2h[ROWS_TOTAL * 512], g_x2l[ROWS_TOTAL * 512];
__device__ __nv_bfloat16 g_hh [ROWS_TOTAL * 2048], g_hl[ROWS_TOTAL * 2048];
__device__ __nv_bfloat16 g_wah[1536 * 512], g_wal[1536 * 512];
__device__ __nv_bfloat16 g_woh[512 * 512],  g_wol[512 * 512];
__device__ __nv_bfloat16 g_w1h[2048 * 512], g_w1l[2048 * 512];
__device__ __nv_bfloat16 g_w2h[512 * 2048], g_w2l[512 * 2048];

// ---------------------------------------------------------------------------
// helpers
// ---------------------------------------------------------------------------
__device__ __forceinline__ uint32_t smem_u32(const void* p) {
    return (uint32_t)__cvta_generic_to_shared(p);
}
__device__ __forceinline__ void ldsm4(uint32_t* r, uint32_t a) {
    asm volatile("ldmatrix.sync.aligned.m8n8.x4.shared.b16 {%0,%1,%2,%3}, [%4];\n"
                 : "=r"(r[0]), "=r"(r[1]), "=r"(r[2]), "=r"(r[3]) : "r"(a));
}
__device__ __forceinline__ void mma16816(float* d, const uint32_t* a,
                                         const uint32_t* b) {
    asm volatile("mma.sync.aligned.m16n8k16.row.col.f32.bf16.bf16.f32 "
                 "{%0,%1,%2,%3}, {%4,%5,%6,%7}, {%8,%9}, {%0,%1,%2,%3};\n"
                 : "+f"(d[0]), "+f"(d[1]), "+f"(d[2]), "+f"(d[3])
                 : "r"(a[0]), "r"(a[1]), "r"(a[2]), "r"(a[3]),
                   "r"(b[0]), "r"(b[1]));
}
__device__ __forceinline__ void cpa16(uint32_t saddr, const void* gaddr) {
    asm volatile("cp.async.cg.shared.global [%0], [%1], 16;\n"
                 :: "r"(saddr), "l"(gaddr));
}
#define CPA_COMMIT() asm volatile("cp.async.commit_group;\n")
template<int NW>
__device__ __forceinline__ void cp_wait() {
    asm volatile("cp.async.wait_group %0;\n" :: "n"(NW));
}
__device__ __forceinline__ uint32_t split2(float a, float b, uint32_t& lo) {
    __nv_bfloat16 ha = __float2bfloat16(a), hb = __float2bfloat16(b);
    __nv_bfloat16 la = __float2bfloat16(a - __bfloat162float(ha));
    __nv_bfloat16 lb = __float2bfloat16(b - __bfloat162float(hb));
    lo = (uint32_t)__bfloat16_as_ushort(la) |
         ((uint32_t)__bfloat16_as_ushort(lb) << 16);
    return (uint32_t)__bfloat16_as_ushort(ha) |
           ((uint32_t)__bfloat16_as_ushort(hb) << 16);
}

// ---------------------------------------------------------------------------
// k_split: fp32 -> (hi, lo) bf16, elementwise. n % 1024 == 0.
// ---------------------------------------------------------------------------
__global__ void k_split(const float* __restrict__ in,
                        __nv_bfloat16* __restrict__ hi,
                        __nv_bfloat16* __restrict__ lo, int n)
{
    int base = (blockIdx.x * 256 + threadIdx.x) * 4;
    if (base >= n) return;
    float4 v = *(const float4*)(in + base);
    uint32_t l0, l1;
    uint32_t h0 = split2(v.x, v.y, l0);
    uint32_t h1 = split2(v.z, v.w, l1);
    *(uint2*)(hi + base) = make_uint2(h0, h1);
    *(uint2*)(lo + base) = make_uint2(l0, l1);
}

// ===========================================================================
// Tensor-core GEMM: C = A @ B^T + bias. split-bf16, 2-stage cp.async,
// two __syncthreads per k-iter (R9-proven; 2 CTAs/SM).
// EPI: 0 none, 1 exact GELU, 2 += R.  OUT: 0 fp32 C, 1 split bf16 (Ch,Cl).
// ===========================================================================
#define LDSD 40
#define AE   (128 * LDSD)
#define AB   (AE * 2)
#define STAGEB (AB * 4)        // 40960
#define GSMEM  (STAGEB * 2)    // 81920  -> 2 CTAs per SM

template<int EPI, int OUT>
__global__ void __launch_bounds__(256) k_tgemm2(
    const __nv_bfloat16* __restrict__ Ah, const __nv_bfloat16* __restrict__ Al,
    const __nv_bfloat16* __restrict__ Bh, const __nv_bfloat16* __restrict__ Bl,
    const float* __restrict__ bias, const float* __restrict__ R,
    float* __restrict__ C,
    __nv_bfloat16* __restrict__ Ch, __nv_bfloat16* __restrict__ Cl,
    int N, int K)
{
    extern __shared__ __nv_bfloat16 dsm[];
    const uint32_t sbase = smem_u32(dsm);

    const int tid = threadIdx.x;
    const int lane = tid & 31, warp = tid >> 5;
    const int wm = warp & 3, wn = warp >> 2;
    const int m0 = blockIdx.y * 128, n0 = blockIdx.x * 128;

    const int crow = tid >> 2;
    const int ccol = (tid & 3) * 8;
    const __nv_bfloat16* Agh = Ah + (size_t)(m0 + crow) * K + ccol;
    const __nv_bfloat16* Agl = Al + (size_t)(m0 + crow) * K + ccol;
    const __nv_bfloat16* Bgh = Bh + (size_t)(n0 + crow) * K + ccol;
    const __nv_bfloat16* Bgl = Bl + (size_t)(n0 + crow) * K + ccol;
    const uint32_t so_base = (uint32_t)(crow * LDSD + ccol) * 2;
    const uint32_t so_step = (uint32_t)(64 * LDSD) * 2;

    float acc[2][8][4];
#pragma unroll
    for (int i = 0; i < 2; i++)
#pragma unroll
        for (int j = 0; j < 8; j++)
#pragma unroll
            for (int q = 0; q < 4; q++) acc[i][j][q] = 0.f;

    auto issue_stage = [&](int it, int st) {
        const int k0 = it * 32;
        const uint32_t sb = sbase + st * STAGEB;
#pragma unroll
        for (int r2 = 0; r2 < 2; r2++) {
            const size_t go = (size_t)r2 * 64 * K + k0;
            const uint32_t so = so_base + r2 * so_step;
            cpa16(sb + 0 * AB + so, Agh + go);
            cpa16(sb + 1 * AB + so, Agl + go);
            cpa16(sb + 2 * AB + so, Bgh + go);
            cpa16(sb + 3 * AB + so, Bgl + go);
        }
    };

    const int niter = K >> 5;
    issue_stage(0, 0);
    CPA_COMMIT();

    for (int it = 0; it < niter; it++) {
        const int st = it & 1;
        if (it + 1 < niter) { issue_stage(it + 1, st ^ 1); CPA_COMMIT(); }
        if (it + 1 < niter) cp_wait<1>(); else cp_wait<0>();
        __syncthreads();

        const uint32_t sb = sbase + st * STAGEB;
        const uint32_t aH = sb, aL = sb + AB, bH = sb + 2 * AB, bL = sb + 3 * AB;

#pragma unroll
        for (int ks = 0; ks < 2; ks++) {
            const int kk = ks * 16;
            uint32_t ah[2][4], al2[2][4], bh[8][2], bl[8][2];
#pragma unroll
            for (int ms = 0; ms < 2; ms++) {
                int row = wm * 32 + ms * 16 + ((lane >> 3) & 1) * 8 + (lane & 7);
                int col = kk + ((lane >> 4) & 1) * 8;
                uint32_t bo = (uint32_t)(row * LDSD + col) * 2;
                ldsm4(ah[ms], aH + bo);
                ldsm4(al2[ms], aL + bo);
            }
#pragma unroll
            for (int nb = 0; nb < 4; nb++) {
                int rn = wn * 64 + nb * 16 + ((lane >> 4) & 1) * 8 + (lane & 7);
                int col = kk + ((lane >> 3) & 1) * 8;
                uint32_t bo = (uint32_t)(rn * LDSD + col) * 2;
                uint32_t t4[4];
                ldsm4(t4, bH + bo);
                bh[2 * nb][0] = t4[0]; bh[2 * nb][1] = t4[1];
                bh[2 * nb + 1][0] = t4[2]; bh[2 * nb + 1][1] = t4[3];
                ldsm4(t4, bL + bo);
                bl[2 * nb][0] = t4[0]; bl[2 * nb][1] = t4[1];
                bl[2 * nb + 1][0] = t4[2]; bl[2 * nb + 1][1] = t4[3];
            }
#pragma unroll
            for (int ms = 0; ms < 2; ms++)
#pragma unroll
                for (int ns = 0; ns < 8; ns++) {
                    mma16816(acc[ms][ns], ah[ms], bh[ns]);
                    mma16816(acc[ms][ns], ah[ms], bl[ns]);
                    mma16816(acc[ms][ns], al2[ms], bh[ns]);
                }
        }
        __syncthreads();
    }

    const int tg = lane >> 2, tq = lane & 3;
#pragma unroll
    for (int ms = 0; ms < 2; ms++) {
        int row0 = m0 + wm * 32 + ms * 16 + tg;
#pragma unroll
        for (int ns = 0; ns < 8; ns++) {
            int col = n0 + wn * 64 + ns * 8 + tq * 2;
            float b0 = bias[col], b1 = bias[col + 1];
            float v[4];
            v[0] = acc[ms][ns][0] + b0; v[1] = acc[ms][ns][1] + b1;
            v[2] = acc[ms][ns][2] + b0; v[3] = acc[ms][ns][3] + b1;
            if (EPI == 1) {
#pragma unroll
                for (int q = 0; q < 4; q++)
                    v[q] = 0.5f * v[q] *
                           (1.0f + erff(v[q] * 0.7071067811865476f));
            }
            size_t o0 = (size_t)row0 * N + col;
            size_t o1 = (size_t)(row0 + 8) * N + col;
            if (EPI == 2) {
                float2 r0 = *(const float2*)(R + o0);
                float2 r1 = *(const float2*)(R + o1);
                v[0] += r0.x; v[1] += r0.y; v[2] += r1.x; v[3] += r1.y;
            }
            if (OUT == 0) {
                *(float2*)(C + o0) = make_float2(v[0], v[1]);
                *(float2*)(C + o1) = make_float2(v[2], v[3]);
            } else {
                uint32_t l0, l1;
                uint32_t h0 = split2(v[0], v[1], l0);
                uint32_t h1 = split2(v[2], v[3], l1);
                *(uint32_t*)(Ch + o0) = h0; *(uint32_t*)(Cl + o0) = l0;
                *(uint32_t*)(Ch + o1) = h1; *(uint32_t*)(Cl + o1) = l1;
            }
        }
    }
}

// ===========================================================================
// Tensor-core flash attention v2: consumes split-bf16 qkv.
// Q + K via cp.async (K double-buffered); V fill = bf16 register scatter.
// ===========================================================================
#define QSTRIDE 136
#define VSTRIDE 72
#define FA_QE (128 * QSTRIDE)       // 17408
#define FA_KE (64 * QSTRIDE)        // 8704
#define FA_VE (128 * VSTRIDE)       // 9216
#define FA_ELEMS (2*FA_QE + 4*FA_KE + 2*FA_VE)   // 88064
#define FA_SMEM (FA_ELEMS * 2)                   // 176128 B

__global__ void __launch_bounds__(256, 1) k_attn_tc(
    const __nv_bfloat16* __restrict__ qkvh,
    const __nv_bfloat16* __restrict__ qkvl,
    __nv_bfloat16* __restrict__ oh, __nv_bfloat16* __restrict__ ol)
{
    extern __shared__ __nv_bfloat16 smb[];
    __nv_bfloat16* sQh = smb;
    __nv_bfloat16* sQl = smb + FA_QE;
    __nv_bfloat16* sKh = smb + 2 * FA_QE;                 // two stages
    __nv_bfloat16* sKl = smb + 2 * FA_QE + 2 * FA_KE;     // two stages
    __nv_bfloat16* sVh = smb + 2 * FA_QE + 4 * FA_KE;
    __nv_bfloat16* sVl = smb + 2 * FA_QE + 4 * FA_KE + FA_VE;

    const int tid = threadIdx.x, lane = tid & 31, warp = tid >> 5;
    const int qt = blockIdx.x, bh = blockIdx.y;
    const int b = bh >> 2, h = bh & 3;
    const size_t bhbase = (size_t)b * 512 * 1536 + h * 128;
    const float scale = 0.08838834764831845f;   // 1/sqrt(128)

    const uint32_t uQh = smem_u32(sQh), uQl = smem_u32(sQl);
    const uint32_t uKh = smem_u32(sKh), uKl = smem_u32(sKl);
    const uint32_t uVh = smem_u32(sVh), uVl = smem_u32(sVl);

    // ---- Q tile via cp.async ----
    {
        int r = tid >> 1, c0 = (tid & 1) * 64;
        const __nv_bfloat16* gqh = qkvh + bhbase + (size_t)(qt * 128 + r) * 1536 + c0;
        const __nv_bfloat16* gql = qkvl + bhbase + (size_t)(qt * 128 + r) * 1536 + c0;
        uint32_t so = (uint32_t)(r * QSTRIDE + c0) * 2;
#pragma unroll
        for (int i = 0; i < 8; i++) cpa16(uQh + so + i * 16, gqh + i * 8);
#pragma unroll
        for (int i = 0; i < 8; i++) cpa16(uQl + so + i * 16, gql + i * 8);
    }
    CPA_COMMIT();

    auto issueK = [&](int kc, int st) {
        int r = tid >> 2, c0 = (tid & 3) * 32;
        const __nv_bfloat16* gkh =
            qkvh + bhbase + (size_t)(kc * 64 + r) * 1536 + 512 + c0;
        const __nv_bfloat16* gkl =
            qkvl + bhbase + (size_t)(kc * 64 + r) * 1536 + 512 + c0;
        uint32_t so = (uint32_t)(r * QSTRIDE + c0) * 2;
        uint32_t sto = (uint32_t)(st * FA_KE) * 2;
#pragma unroll
        for (int i = 0; i < 4; i++) cpa16(uKh + sto + so + i * 16, gkh + i * 8);
#pragma unroll
        for (int i = 0; i < 4; i++) cpa16(uKl + sto + so + i * 16, gkl + i * 8);
    };

    issueK(0, 0);
    CPA_COMMIT();

    float o[16][4];
#pragma unroll
    for (int j = 0; j < 16; j++)
#pragma unroll
        for (int q = 0; q < 4; q++) o[j][q] = 0.f;
    float mr0 = -INFINITY, mr1 = -INFINITY, lr0 = 0.f, lr1 = 0.f;

    for (int kc = 0; kc < 8; kc++) {
        const int st = kc & 1;
        __syncthreads();      // V buffer free (PV kc-1 done); K stage st^1 free

        // ---- V fill: bf16 pairs, conflict-free scatter (d = 2q + 8i) ----
        {
            int r = tid >> 2, q = tid & 3;
            const size_t vg = bhbase + (size_t)(kc * 64 + r) * 1536 + 1024;
#pragma unroll
            for (int i = 0; i < 16; i++) {
                int d = q * 2 + i * 8;
                __nv_bfloat162 vh = *(const __nv_bfloat162*)(qkvh + vg + d);
                __nv_bfloat162 vl = *(const __nv_bfloat162*)(qkvl + vg + d);
                sVh[d * VSTRIDE + r] = vh.x; sVh[(d + 1) * VSTRIDE + r] = vh.y;
                sVl[d * VSTRIDE + r] = vl.x; sVl[(d + 1) * VSTRIDE + r] = vl.y;
            }
        }
        if (kc + 1 < 8) { issueK(kc + 1, st ^ 1); CPA_COMMIT(); }
        if (kc + 1 < 8) cp_wait<1>(); else cp_wait<0>();
        __syncthreads();

        const uint32_t kH = uKh + (uint32_t)(st * FA_KE) * 2;
        const uint32_t kL = uKl + (uint32_t)(st * FA_KE) * 2;

        // ---- scores: S(16 x 64) per warp ----
        float sc[8][4];
#pragma unroll
        for (int j = 0; j < 8; j++)
#pragma unroll
            for (int q = 0; q < 4; q++) sc[j][q] = 0.f;

#pragma unroll
        for (int ks = 0; ks < 8; ks++) {
            const int kk = ks * 16;
            uint32_t ah[4], al2[4];
            int arow = warp * 16 + ((lane >> 3) & 1) * 8 + (lane & 7);
            int acol = kk + ((lane >> 4) & 1) * 8;
            uint32_t ao = (uint32_t)(arow * QSTRIDE + acol) * 2;
            ldsm4(ah, uQh + ao);
            ldsm4(al2, uQl + ao);
#pragma unroll
            for (int nb = 0; nb < 4; nb++) {
                int rn = nb * 16 + ((lane >> 4) & 1) * 8 + (lane & 7);
                int col = kk + ((lane >> 3) & 1) * 8;
                uint32_t bo = (uint32_t)(rn * QSTRIDE + col) * 2;
                uint32_t th[4], tl[4];
                ldsm4(th, kH + bo);
                ldsm4(tl, kL + bo);
                uint32_t b0h[2] = {th[0], th[1]}, b1h[2] = {th[2], th[3]};
                uint32_t b0l[2] = {tl[0], tl[1]}, b1l[2] = {tl[2], tl[3]};
                mma16816(sc[2*nb],   ah, b0h);
                mma16816(sc[2*nb],   ah, b0l);
                mma16816(sc[2*nb],   al2, b0h);
                mma16816(sc[2*nb+1], ah, b1h);
                mma16816(sc[2*nb+1], ah, b1l);
                mma16816(sc[2*nb+1], al2, b1h);
            }
        }

        // ---- online softmax ----
        float mx0 = -INFINITY, mx1 = -INFINITY;
#pragma unroll
        for (int j = 0; j < 8; j++) {
#pragma unroll
            for (int q = 0; q < 4; q++) sc[j][q] *= scale;
            mx0 = fmaxf(mx0, fmaxf(sc[j][0], sc[j][1]));
            mx1 = fmaxf(mx1, fmaxf(sc[j][2], sc[j][3]));
        }
        mx0 = fmaxf(mx0, __shfl_xor_sync(0xffffffffu, mx0, 1));
        mx0 = fmaxf(mx0, __shfl_xor_sync(0xffffffffu, mx0, 2));
        mx1 = fmaxf(mx1, __shfl_xor_sync(0xffffffffu, mx1, 1));
        mx1 = fmaxf(mx1, __shfl_xor_sync(0xffffffffu, mx1, 2));
        float mn0 = fmaxf(mr0, mx0), mn1 = fmaxf(mr1, mx1);
        float a0 = __expf(mr0 - mn0), a1 = __expf(mr1 - mn1);

        uint32_t phk[8][2], plk[8][2];
        float s0 = 0.f, s1 = 0.f;
#pragma unroll
        for (int j = 0; j < 8; j++) {
            float p0 = __expf(sc[j][0] - mn0);
            float p1 = __expf(sc[j][1] - mn0);
            float p2 = __expf(sc[j][2] - mn1);
            float p3 = __expf(sc[j][3] - mn1);
            s0 += p0 + p1; s1 += p2 + p3;
            phk[j][0] = split2(p0, p1, plk[j][0]);
            phk[j][1] = split2(p2, p3, plk[j][1]);
        }
        s0 += __shfl_xor_sync(0xffffffffu, s0, 1);
        s0 += __shfl_xor_sync(0xffffffffu, s0, 2);
        s1 += __shfl_xor_sync(0xffffffffu, s1, 1);
        s1 += __shfl_xor_sync(0xffffffffu, s1, 2);
        lr0 = lr0 * a0 + s0;
        lr1 = lr1 * a1 + s1;
#pragma unroll
        for (int j = 0; j < 16; j++) {
            o[j][0] *= a0; o[j][1] *= a0;
            o[j][2] *= a1; o[j][3] *= a1;
        }
        mr0 = mn0; mr1 = mn1;

        // ---- P @ V ----
#pragma unroll
        for (int jp = 0; jp < 4; jp++) {
            uint32_t pah[4] = {phk[2*jp][0], phk[2*jp][1],
                               phk[2*jp+1][0], phk[2*jp+1][1]};
            uint32_t pal[4] = {plk[2*jp][0], plk[2*jp][1],
                               plk[2*jp+1][0], plk[2*jp+1][1]};
            int col = jp * 16 + ((lane >> 3) & 1) * 8;
#pragma unroll
            for (int nb = 0; nb < 8; nb++) {
                int rn = nb * 16 + ((lane >> 4) & 1) * 8 + (lane & 7);
                uint32_t bo = (uint32_t)(rn * VSTRIDE + col) * 2;
                uint32_t th[4], tl[4];
                ldsm4(th, uVh + bo);
                ldsm4(tl, uVl + bo);
                uint32_t b0h[2] = {th[0], th[1]}, b1h[2] = {th[2], th[3]};
                uint32_t b0l[2] = {tl[0], tl[1]}, b1l[2] = {tl[2], tl[3]};
                mma16816(o[2*nb],   pah, b0h);
                mma16816(o[2*nb],   pah, b0l);
                mma16816(o[2*nb],   pal, b0h);
                mma16816(o[2*nb+1], pah, b1h);
                mma16816(o[2*nb+1], pah, b1l);
                mma16816(o[2*nb+1], pal, b1h);
            }
        }
    }

    // ---- epilogue ----
    const int g = lane >> 2, q = lane & 3;
    const int row0 = qt * 128 + warp * 16 + g;
    const float i0 = 1.f / lr0, i1 = 1.f / lr1;
#pragma unroll
    for (int j = 0; j < 16; j++) {
        int col = h * 128 + j * 8 + q * 2;
        size_t off0 = ((size_t)b * 512 + row0) * 512 + col;
        size_t off1 = off0 + (size_t)8 * 512;
        uint32_t lo;
        uint32_t hi = split2(o[j][0] * i0, o[j][1] * i0, lo);
        *(uint32_t*)(oh + off0) = hi; *(uint32_t*)(ol + off0) = lo;
        hi = split2(o[j][2] * i1, o[j][3] * i1, lo);
        *(uint32_t*)(oh + off1) = hi; *(uint32_t*)(ol + off1) = lo;
    }
}

// ===========================================================================
// LayerNorm (LN2 final): one warp per row.
// ===========================================================================
__global__ void k_ln(const float* __restrict__ in, const float* __restrict__ g,
                     const float* __restrict__ b, float* __restrict__ out)
{
    const int warp = threadIdx.x >> 5, lane = threadIdx.x & 31;
    const int row = blockIdx.x * 8 + warp;
    const float* p = in + (size_t)row * 512;
    float v[16]; float s = 0.f;
#pragma unroll
    for (int j = 0; j < 16; j++) { v[j] = p[j * 32 + lane]; s += v[j]; }
#pragma unroll
    for (int m = 16; m > 0; m >>= 1) s += __shfl_xor_sync(0xffffffffu, s, m);
    float mean = s * (1.f / 512.f);
    float vs = 0.f;
#pragma unroll
    for (int j = 0; j < 16; j++) { float d = v[j] - mean; vs += d * d; }
#pragma unroll
    for (int m = 16; m > 0; m >>= 1) vs += __shfl_xor_sync(0xffffffffu, vs, m);
    float inv = rsqrtf(vs * (1.f / 512.f) + 1e-5f);
    float* o = out + (size_t)row * 512;
#pragma unroll
    for (int j = 0; j < 16; j++) {
        int c = j * 32 + lane;
        o[c] = (v[j] - mean) * inv * g[c] + b[c];
    }
}

// ===========================================================================
// Fused: x1 = LN1(y); ang = LN3(x1) @ qin_w^T + qin_b.
// ===========================================================================
__global__ void k_ln1_ang(const float* __restrict__ y,
                          const float* __restrict__ g1, const float* __restrict__ b1,
                          const float* __restrict__ g3, const float* __restrict__ b3,
                          const float* __restrict__ qw, const float* __restrict__ qb,
                          float* __restrict__ x1, float* __restrict__ ang)
{
    const int warp = threadIdx.x >> 5, lane = threadIdx.x & 31;
    const int row = blockIdx.x * 8 + warp;
    const float* p = y + (size_t)row * 512;
    float v[16]; float s = 0.f;
#pragma unroll
    for (int j = 0; j < 16; j++) { v[j] = p[j * 32 + lane]; s += v[j]; }
#pragma unroll
    for (int m = 16; m > 0; m >>= 1) s += __shfl_xor_sync(0xffffffffu, s, m);
    float mean = s * (1.f / 512.f);
    float vs = 0.f;
#pragma unroll
    for (int j = 0; j < 16; j++) { float d = v[j] - mean; vs += d * d; }
#pragma unroll
    for (int m = 16; m > 0; m >>= 1) vs += __shfl_xor_sync(0xffffffffu, vs, m);
    float inv = rsqrtf(vs * (1.f / 512.f) + 1e-5f);
    float n1[16];
    float* o = x1 + (size_t)row * 512;
    float s2 = 0.f;
#pragma unroll
    for (int j = 0; j < 16; j++) {
        int c = j * 32 + lane;
        n1[j] = (v[j] - mean) * inv * g1[c] + b1[c];
        o[c] = n1[j];
        s2 += n1[j];
    }
#pragma unroll
    for (int m = 16; m > 0; m >>= 1) s2 += __shfl_xor_sync(0xffffffffu, s2, m);
    float mean2 = s2 * (1.f / 512.f);
    float vs2 = 0.f;
#pragma unroll
    for (int j = 0; j < 16; j++) { float d = n1[j] - mean2; vs2 += d * d; }
#pragma unroll
    for (int m = 16; m > 0; m >>= 1) vs2 += __shfl_xor_sync(0xffffffffu, vs2, m);
    float inv2 = rsqrtf(vs2 * (1.f / 512.f) + 1e-5f);
    float nn[16];
#pragma unroll
    for (int j = 0; j < 16; j++) {
        int c = j * 32 + lane;
        nn[j] = (n1[j] - mean2) * inv2 * g3[c] + b3[c];
    }
#pragma unroll
    for (int q = 0; q < 8; q++) {
        const float* w = qw + q * 512;
        float d = 0.f;
#pragma unroll
        for (int j = 0; j < 16; j++) d = fmaf(nn[j], w[j * 32 + lane], d);
#pragma unroll
        for (int m = 16; m > 0; m >>= 1) d += __shfl_xor_sync(0xffffffffu, d, m);
        if (lane == 0) ang[(size_t)row * 8 + q] = d + qb[q];
    }
}

// ===========================================================================
// Quantum circuit: one warp per sample. 256 complex amps: 8 per lane.
// ===========================================================================
template<int B>
__device__ __forceinline__ void rx_b(float (&xr)[8], float (&xi)[8],
                                     float c, float sn)
{
    if (B >= 3) {
        const int lm = 1 << (B - 3);
#pragma unroll
        for (int r = 0; r < 8; r++) {
            float pr = __shfl_xor_sync(0xffffffffu, xr[r], lm);
            float pi = __shfl_xor_sync(0xffffffffu, xi[r], lm);
            float nr = c * xr[r] + sn * pi;
            float ni = c * xi[r] - sn * pr;
            xr[r] = nr; xi[r] = ni;
        }
    } else {
        const int m = 1 << B;
#pragma unroll
        for (int r = 0; r < 8; r++) {
            if (!(r & m)) {
                int r1 = r | m;
                float ar = xr[r], ai = xi[r], br = xr[r1], bi = xi[r1];
                xr[r]  = c * ar + sn * bi;  xi[r]  = c * ai - sn * br;
                xr[r1] = c * br + sn * ai;  xi[r1] = c * bi - sn * ar;
            }
        }
    }
}

template<int B>
__device__ __forceinline__ void rz_b(float (&xr)[8], float (&xi)[8],
                                     float ch, float sh, int lane)
{
#pragma unroll
    for (int r = 0; r < 8; r++) {
        int bit = (B >= 3) ? ((lane >> (B - 3)) & 1) : ((r >> B) & 1);
        float sgn = bit ? sh : -sh;
        float x = xr[r], y = xi[r];
        xr[r] = x * ch - sgn * y;
        xi[r] = fmaf(x, sgn, y * ch);
    }
}

template<int C>
__device__ __forceinline__ void cnot_c(float (&xr)[8], float (&xi)[8], int lane)
{
    const int cb = 7 - C, tb = 6 - C;
    if (C <= 3) {
        const int lc = 1 << (cb - 3);
        const int tm = 1 << (tb - 3);
        bool ctl = (lane & lc) != 0;
#pragma unroll
        for (int r = 0; r < 8; r++) {
            float pr = __shfl_xor_sync(0xffffffffu, xr[r], tm);
            float pi = __shfl_xor_sync(0xffffffffu, xi[r], tm);
            if (ctl) { xr[r] = pr; xi[r] = pi; }
        }
    } else if (C == 4) {
        if (lane & 1) {
#pragma unroll
            for (int r = 0; r < 4; r++) {
                float t = xr[r]; xr[r] = xr[r + 4]; xr[r + 4] = t;
                t = xi[r]; xi[r] = xi[r + 4]; xi[r + 4] = t;
            }
        }
    } else {
        const int cm = 1 << cb, tm = 1 << tb;
#pragma unroll
        for (int r = 0; r < 8; r++) {
            if ((r & cm) && !(r & tm)) {
                int r1 = r | tm;
                float t = xr[r]; xr[r] = xr[r1]; xr[r1] = t;
                t = xi[r]; xi[r] = xi[r1]; xi[r1] = t;
            }
        }
    }
}

#define DO_RXRZ(BIT, THX, THZ) do {                         \
    float h_, c_, s_;                                       \
    h_ = 0.5f * (THX); sincosf(h_, &s_, &c_);               \
    rx_b<BIT>(xr, xi, c_, s_);                              \
    h_ = 0.5f * (THZ); sincosf(h_, &s_, &c_);               \
    rz_b<BIT>(xr, xi, c_, s_, lane);                        \
} while (0)

__global__ void k_quantum(const float* __restrict__ ang,
                          const float* __restrict__ qw,
                          float* __restrict__ zv)
{
    const int warp = threadIdx.x >> 5, lane = threadIdx.x & 31;
    const int row = blockIdx.x * 8 + warp;
    float a[8];
#pragma unroll
    for (int i = 0; i < 8; i++) a[i] = ang[(size_t)row * 8 + i];

    float xr[8], xi[8];
#pragma unroll
    for (int r = 0; r < 8; r++) { xr[r] = 0.f; xi[r] = 0.f; }
    if (lane == 0) xr[0] = 1.f;

    DO_RXRZ(7, a[0], a[0]);
    DO_RXRZ(6, a[1], a[1]);
    DO_RXRZ(5, a[2], a[2]);
    DO_RXRZ(4, a[3], a[3]);
    DO_RXRZ(3, a[4], a[4]);
    DO_RXRZ(2, a[5], a[5]);
    DO_RXRZ(1, a[6], a[6]);
    DO_RXRZ(0, a[7], a[7]);

    for (int l = 0; l < 4; l++) {
        const float* wl = qw + l * 16;
        DO_RXRZ(7, wl[0], wl[8]);
        DO_RXRZ(6, wl[1], wl[9]);
        DO_RXRZ(5, wl[2], wl[10]);
        DO_RXRZ(4, wl[3], wl[11]);
        DO_RXRZ(3, wl[4], wl[12]);
        DO_RXRZ(2, wl[5], wl[13]);
        DO_RXRZ(1, wl[6], wl[14]);
        DO_RXRZ(0, wl[7], wl[15]);
        cnot_c<0>(xr, xi, lane);
        cnot_c<1>(xr, xi, lane);
        cnot_c<2>(xr, xi, lane);
        cnot_c<3>(xr, xi, lane);
        cnot_c<4>(xr, xi, lane);
        cnot_c<5>(xr, xi, lane);
        cnot_c<6>(xr, xi, lane);
    }

    float p[8], tot = 0.f;
#pragma unroll
    for (int r = 0; r < 8; r++) {
        p[r] = xr[r] * xr[r] + xi[r] * xi[r];
        tot += p[r];
    }
    float z[8];
#pragma unroll
    for (int w = 0; w < 5; w++) {
        int lb = 4 - w;
        z[w] = ((lane >> lb) & 1) ? -tot : tot;
    }
#pragma unroll
    for (int w = 5; w < 8; w++) {
        int bb = 7 - w;
        float s = 0.f;
#pragma unroll
        for (int r = 0; r < 8; r++) s += ((r >> bb) & 1) ? -p[r] : p[r];
        z[w] = s;
    }
#pragma unroll
    for (int i = 0; i < 8; i++)
#pragma unroll
        for (int m = 16; m > 0; m >>= 1)
            z[i] += __shfl_xor_sync(0xffffffffu, z[i], m);
    if (lane == 0) {
#pragma unroll
        for (int i = 0; i < 8; i++) zv[(size_t)row * 8 + i] = z[i];
    }
}

// ===========================================================================
// x2 = x1 + z @ qout_w^T + qout_b; also writes split (x2h, x2l).
// ===========================================================================
__global__ void k_qout(const float* __restrict__ x1, const float* __restrict__ zv,
                       const float* __restrict__ qw, const float* __restrict__ qb,
                       float* __restrict__ x2,
                       __nv_bfloat16* __restrict__ x2h,
                       __nv_bfloat16* __restrict__ x2l)
{
    int idx = blockIdx.x * 256 + threadIdx.x;
    int row = idx >> 7;
    int c = (idx & 127) * 4;
    const float* z = zv + (size_t)row * 8;
    float zz[8];
#pragma unroll
    for (int q = 0; q < 8; q++) zz[q] = z[q];
    float4 r = *(const float4*)(x1 + (size_t)row * 512 + c);
    float rv[4] = {r.x, r.y, r.z, r.w};
    float o[4];
#pragma unroll
    for (int t = 0; t < 4; t++) {
        int col = c + t;
        float acc = qb[col];
        const float* w = qw + col * 8;
#pragma unroll
        for (int q = 0; q < 8; q++) acc = fmaf(zz[q], w[q], acc);
        o[t] = rv[t] + acc;
    }
    size_t off = (size_t)row * 512 + c;
    *(float4*)(x2 + off) = make_float4(o[0], o[1], o[2], o[3]);
    uint32_t l0, l1;
    uint32_t h0 = split2(o[0], o[1], l0);
    uint32_t h1 = split2(o[2], o[3], l1);
    *(uint2*)(x2h + off) = make_uint2(h0, h1);
    *(uint2*)(x2l + off) = make_uint2(l0, l1);
}

// ===========================================================================
extern "C" void kernel_launch(void* const* d_in, const int* in_sizes, int n_in,
                              void* d_out, int out_size)
{
    const float* x          = (const float*)d_in[0];
    const float* attn_in_w  = (const float*)d_in[1];
    const float* attn_in_b  = (const float*)d_in[2];
    const float* attn_out_w = (const float*)d_in[3];
    const float* attn_out_b = (const float*)d_in[4];
    const float* ln1_g      = (const float*)d_in[5];
    const float* ln1_b      = (const float*)d_in[6];
    const float* ln2_g      = (const float*)d_in[7];
    const float* ln2_b      = (const float*)d_in[8];
    const float* ln3_g      = (const float*)d_in[9];
    const float* ln3_b      = (const float*)d_in[10];
    const float* qin_w      = (const float*)d_in[11];
    const float* qin_b      = (const float*)d_in[12];
    const float* qweights   = (const float*)d_in[13];
    const float* qout_w     = (const float*)d_in[14];
    const float* qout_b     = (const float*)d_in[15];
    const float* ffn_w1     = (const float*)d_in[16];
    const float* ffn_b1     = (const float*)d_in[17];
    const float* ffn_w2     = (const float*)d_in[18];
    const float* ffn_b2     = (const float*)d_in[19];
    float* out = (float*)d_out;

    float *y, *x1, *x2, *ang, *zv;
    __nv_bfloat16 *qkvh, *qkvl, *xh, *xl, *ah, *al, *x2h, *x2l, *hh, *hl;
    __nv_bfloat16 *wah, *wal, *woh, *wol, *w1h, *w1l, *w2h, *w2l;
    cudaGetSymbolAddress((void**)&y,    g_y);
    cudaGetSymbolAddress((void**)&x1,   g_x1);
    cudaGetSymbolAddress((void**)&x2,   g_x2);
    cudaGetSymbolAddress((void**)&ang,  g_ang);
    cudaGetSymbolAddress((void**)&zv,   g_zv);
    cudaGetSymbolAddress((void**)&qkvh, g_qkvh);
    cudaGetSymbolAddress((void**)&qkvl, g_qkvl);
    cudaGetSymbolAddress((void**)&xh,   g_xh);
    cudaGetSymbolAddress((void**)&xl,   g_xl);
    cudaGetSymbolAddress((void**)&ah,   g_ah);
    cudaGetSymbolAddress((void**)&al,   g_al);
    cudaGetSymbolAddress((void**)&x2h,  g_x2h);
    cudaGetSymbolAddress((void**)&x2l,  g_x2l);
    cudaGetSymbolAddress((void**)&hh,   g_hh);
    cudaGetSymbolAddress((void**)&hl,   g_hl);
    cudaGetSymbolAddress((void**)&wah,  g_wah);
    cudaGetSymbolAddress((void**)&wal,  g_wal);
    cudaGetSymbolAddress((void**)&woh,  g_woh);
    cudaGetSymbolAddress((void**)&wol,  g_wol);
    cudaGetSymbolAddress((void**)&w1h,  g_w1h);
    cudaGetSymbolAddress((void**)&w1l,  g_w1l);
    cudaGetSymbolAddress((void**)&w2h,  g_w2h);
    cudaGetSymbolAddress((void**)&w2l,  g_w2l);

    cudaFuncSetAttribute(k_attn_tc,
                         cudaFuncAttributeMaxDynamicSharedMemorySize, FA_SMEM);
    cudaFuncSetAttribute(k_tgemm2<0,1>,
                         cudaFuncAttributeMaxDynamicSharedMemorySize, GSMEM);
    cudaFuncSetAttribute(k_tgemm2<2,0>,
                         cudaFuncAttributeMaxDynamicSharedMemorySize, GSMEM);
    cudaFuncSetAttribute(k_tgemm2<1,1>,
                         cudaFuncAttributeMaxDynamicSharedMemorySize, GSMEM);

    // 0. split input + weights to (hi, lo) bf16
    k_split<<<ROWS_TOTAL * 512 / 1024, 256>>>(x, xh, xl, ROWS_TOTAL * 512);
    k_split<<<1536 * 512 / 1024, 256>>>(attn_in_w, wah, wal, 1536 * 512);
    k_split<<<512 * 512 / 1024, 256>>>(attn_out_w, woh, wol, 512 * 512);
    k_split<<<2048 * 512 / 1024, 256>>>(ffn_w1, w1h, w1l, 2048 * 512);
    k_split<<<512 * 2048 / 1024, 256>>>(ffn_w2, w2h, w2l, 512 * 2048);

    // 1. QKV projection -> split bf16 qkv
    k_tgemm2<0,1><<<dim3(12, 128), 256, GSMEM>>>(xh, xl, wah, wal, attn_in_b,
                                                 nullptr, nullptr, qkvh, qkvl,
                                                 1536, 512);
    // 2. Attention (tensor core, bf16 in, split bf16 out)
    k_attn_tc<<<dim3(4, 128), 256, FA_SMEM>>>(qkvh, qkvl, ah, al);
    // 3. Output projection + residual x -> y
    k_tgemm2<2,0><<<dim3(4, 128), 256, GSMEM>>>(ah, al, woh, wol, attn_out_b,
                                                x, y, nullptr, nullptr,
                                                512, 512);
    // 4+5. x1 = LN1(y); angles = LN3(x1) @ qin_w^T + qin_b
    k_ln1_ang<<<2048, 256>>>(y, ln1_g, ln1_b, ln3_g, ln3_b, qin_w, qin_b,
                             x1, ang);
    // 6. quantum expvals
    k_quantum<<<2048, 256>>>(ang, qweights, zv);
    // 7. x2 = x1 + z @ qout_w^T + qout_b (fp32 + split)
    k_qout<<<8192, 256>>>(x1, zv, qout_w, qout_b, x2, x2h, x2l);
    // 8. h = gelu(x2 @ ffn_w1^T + b1), split output
    k_tgemm2<1,1><<<dim3(16, 128), 256, GSMEM>>>(x2h, x2l, w1h, w1l, ffn_b1,
                                                 nullptr, nullptr, hh, hl,
                                                 2048, 512);
    // 9. y = h @ ffn_w2^T + b2 + x2
    k_tgemm2<2,0><<<dim3(4, 128), 256, GSMEM>>>(hh, hl, w2h, w2l, ffn_b2,
                                                x2, y, nullptr, nullptr,
                                                512, 2048);
    // 10. out = LN2(y)
    k_ln<<<2048, 256>>>(y, ln2_g, ln2_b, out);
}